// round 9
// baseline (speedup 1.0000x reference)
#include <cuda_runtime.h>
#include <cuda_fp16.h>
#include <cstdint>

#define NROWS 8192
#define DIN   512
#define DOUT  512

// ---------------- fp16 mma.sync gemm tiling ----------------
#define CTAM 128
#define CTAN 128
#define CTAK 32
#define NSTAGE 4
#define ROWB 80                     // 32 halves (64B) + 16B pad
#define ABYTES (CTAM * ROWB)        // 10240
#define BBYTES (CTAN * ROWB)        // 10240
#define STAGEB (ABYTES + BBYTES)    // 20480
#define DYN_SMEM (STAGEB * NSTAGE)  // 81920 per CTA (x2 CTAs = 160KB/SM)

#define NT1 (NROWS / CTAK)          // 256 k-tiles for gemm1
#define NT2 (DIN / CTAK)            // 16 k-tiles for gemm2

// Scratch (allocation-free)
__device__ __half g_adj_h[(size_t)NROWS * NROWS];    // fp16 adjacency
__device__ float  g_deg[NROWS];
__device__ __half g_xsT[(size_t)DIN * NROWS];        // xsT[n][k] = half(d_k * x[k][n])
__device__ __half g_support[(size_t)NROWS * DIN];    // fp16 intermediate
__device__ __half g_Wh[(size_t)DOUT * DIN];          // fp16 weights [n][k]

// ======================= PTX helpers =======================
__device__ __forceinline__ uint32_t smem_u32(const void* p) {
    uint32_t a;
    asm("{ .reg .u64 t; cvta.to.shared.u64 t, %1; cvt.u32.u64 %0, t; }" : "=r"(a) : "l"(p));
    return a;
}

__device__ __forceinline__ uint32_t h2_bits(__half2 h) {
    return *reinterpret_cast<uint32_t*>(&h);
}

#define CP_ASYNC16(dst, src) \
    asm volatile("cp.async.cg.shared.global [%0], [%1], 16;" :: "r"(dst), "l"(src))
#define CP_COMMIT() asm volatile("cp.async.commit_group;" ::: "memory")
#define CP_WAITG2() asm volatile("cp.async.wait_group 2;" ::: "memory")

#define LDSM4(r0, r1, r2, r3, addr)                                             \
    asm volatile("ldmatrix.sync.aligned.m8n8.x4.shared.b16 {%0,%1,%2,%3}, [%4];"\
                 : "=r"(r0), "=r"(r1), "=r"(r2), "=r"(r3) : "r"(addr))

#define MMA_F16(d, a, b0, b1)                                                   \
    asm volatile(                                                               \
        "mma.sync.aligned.m16n8k16.row.col.f32.f16.f16.f32 "                    \
        "{%0,%1,%2,%3}, {%4,%5,%6,%7}, {%8,%9}, {%0,%1,%2,%3};"                 \
        : "+f"((d)[0]), "+f"((d)[1]), "+f"((d)[2]), "+f"((d)[3])                \
        : "r"((a)[0]), "r"((a)[1]), "r"((a)[2]), "r"((a)[3]),                   \
          "r"(b0), "r"(b1))

// ---------------------------------------------------------------------------
// Kernel 1: d[i] = rsqrt(1 + sum_j adj[i][j])  AND  g_adj_h = half(adj)
// ---------------------------------------------------------------------------
__global__ __launch_bounds__(256) void rowsum_convert(const float* __restrict__ adj) {
    const int row = blockIdx.x;
    const float4* p = reinterpret_cast<const float4*>(adj + (size_t)row * NROWS);
    uint4* dst = reinterpret_cast<uint4*>(g_adj_h + (size_t)row * NROWS);
    float s = 0.f;
    for (int i = threadIdx.x; i < NROWS / 8; i += 256) {
        float4 v0 = p[2 * i + 0];
        float4 v1 = p[2 * i + 1];
        s += ((v0.x + v0.y) + (v0.z + v0.w)) + ((v1.x + v1.y) + (v1.z + v1.w));
        uint4 o;
        o.x = h2_bits(__floats2half2_rn(v0.x, v0.y));
        o.y = h2_bits(__floats2half2_rn(v0.z, v0.w));
        o.z = h2_bits(__floats2half2_rn(v1.x, v1.y));
        o.w = h2_bits(__floats2half2_rn(v1.z, v1.w));
        dst[i] = o;
    }
#pragma unroll
    for (int o = 16; o > 0; o >>= 1) s += __shfl_xor_sync(0xffffffffu, s, o);
    __shared__ float ws[8];
    if ((threadIdx.x & 31) == 0) ws[threadIdx.x >> 5] = s;
    __syncthreads();
    if (threadIdx.x == 0) {
        float t = 0.f;
#pragma unroll
        for (int i = 0; i < 8; i++) t += ws[i];
        g_deg[row] = rsqrtf(1.0f + t);
    }
}

// ---------------------------------------------------------------------------
// Kernel 2: xsT[n][k] = half( d_k * x[k][n] )   (scaled transpose)
// ---------------------------------------------------------------------------
__global__ __launch_bounds__(256) void scale_transpose_h(const float* __restrict__ x) {
    __shared__ float tile[32][33];
    const int kb = blockIdx.x * 32;
    const int nb = blockIdx.y * 32;
    const int tx = threadIdx.x & 31;
    const int ty = threadIdx.x >> 5;
#pragma unroll
    for (int i = 0; i < 32; i += 8) {
        int k = kb + ty + i;
        tile[ty + i][tx] = g_deg[k] * x[(size_t)k * DIN + nb + tx];
    }
    __syncthreads();
#pragma unroll
    for (int i = 0; i < 32; i += 8) {
        int n = nb + ty + i;
        g_xsT[(size_t)n * NROWS + kb + tx] = __float2half_rn(tile[tx][ty + i]);
    }
}

// ---------------------------------------------------------------------------
// Kernel 3: W fp32 -> fp16
// ---------------------------------------------------------------------------
__global__ __launch_bounds__(256) void w_convert(const float* __restrict__ W) {
    const int i = blockIdx.x * 256 + threadIdx.x;
    float4 v = reinterpret_cast<const float4*>(W)[i];
    __half2* d = reinterpret_cast<__half2*>(g_Wh) + 2 * i;
    d[0] = __floats2half2_rn(v.x, v.y);
    d[1] = __floats2half2_rn(v.z, v.w);
}

// ===========================================================================
// Gemm core: CTA 128x128, 8 warps (2m x 4n) of 64x32, BK=32, 4-stage cp.async,
// double-buffered ldmatrix fragments, 2 CTAs/SM for barrier/latency overlap.
// ===========================================================================
struct GemmCore {
    uint32_t sbase;
    int m0, n0, wm, wn, lane;
    uint32_t aoff, boff;
};

__device__ __forceinline__ void core_init(GemmCore& c, char* dyn, int bid) {
    const int tid = threadIdx.x;
    const int wid = tid >> 5;
    c.lane = tid & 31;
    c.m0 = (bid >> 2) * CTAM;
    c.n0 = (bid & 3) * CTAN;
    c.wm = (wid & 1) * 64;
    c.wn = (wid >> 1) * 32;
    c.sbase = smem_u32(dyn);
    const int l = c.lane;
    c.aoff = (uint32_t)((l & 15) * ROWB + ((l >> 4) & 1) * 16);
    c.boff = (uint32_t)(((l & 7) + ((l >> 4) & 1) * 8) * ROWB + ((l >> 3) & 1) * 16);
}

// Load one 32-k tile into its stage slot. 1024 16B chunks / 256 threads.
__device__ __forceinline__ void load_tile(const GemmCore& c,
                                          const __half* __restrict__ Ag, int strideA,
                                          const __half* __restrict__ Bg, int strideB,
                                          int t) {
    const int tid = threadIdx.x;
    const int k0 = t * CTAK;
    const uint32_t stA = c.sbase + (uint32_t)(t & (NSTAGE - 1)) * STAGEB;
    const uint32_t stB = stA + ABYTES;
#pragma unroll
    for (int i = 0; i < 2; i++) {
        int ch = tid + i * 256;
        int r = ch >> 2, q = ch & 3;
        CP_ASYNC16(stA + (uint32_t)(r * ROWB + q * 16),
                   Ag + (size_t)(c.m0 + r) * strideA + k0 + q * 8);
    }
#pragma unroll
    for (int i = 0; i < 2; i++) {
        int ch = tid + i * 256;
        int r = ch >> 2, q = ch & 3;
        CP_ASYNC16(stB + (uint32_t)(r * ROWB + q * 16),
                   Bg + (size_t)(c.n0 + r) * strideB + k0 + q * 8);
    }
}

// Load all fragments for k-half s (s in {0,1}) of tile t.
__device__ __forceinline__ void lds_frags(const GemmCore& c, int t, int s,
                                          uint32_t a[4][4], uint32_t b[4][2]) {
    const uint32_t stA = c.sbase + (uint32_t)(t & (NSTAGE - 1)) * STAGEB;
    const uint32_t stB = stA + ABYTES;
#pragma unroll
    for (int i = 0; i < 4; i++)
        LDSM4(a[i][0], a[i][1], a[i][2], a[i][3],
              stA + (uint32_t)((c.wm + 16 * i) * ROWB + s * 32) + c.aoff);
#pragma unroll
    for (int jp = 0; jp < 2; jp++)
        LDSM4(b[2 * jp][0], b[2 * jp][1], b[2 * jp + 1][0], b[2 * jp + 1][1],
              stB + (uint32_t)((c.wn + 16 * jp) * ROWB + s * 32) + c.boff);
}

__device__ __forceinline__ void mma_all(float acc[4][4][4],
                                        uint32_t a[4][4], uint32_t b[4][2]) {
#pragma unroll
    for (int i = 0; i < 4; i++)
#pragma unroll
        for (int j = 0; j < 4; j++)
            MMA_F16(acc[i][j], a[i], b[j][0], b[j][1]);
}

// Pipelined mainloop shared by both gemms (R4-proven structure).
__device__ __forceinline__ void gemm_mainloop(const GemmCore& c,
                                              const __half* __restrict__ Ag, int strideA,
                                              const __half* __restrict__ Bg, int strideB,
                                              int ntiles, float acc[4][4][4]) {
    // prologue: stages 0..2
#pragma unroll
    for (int s = 0; s < NSTAGE - 1; s++) {
        load_tile(c, Ag, strideA, Bg, strideB, s);
        CP_COMMIT();
    }
    CP_WAITG2();                 // tile 0 resident
    __syncthreads();

    uint32_t a0[4][4], b0[4][2], a1[4][4], b1[4][2];
    lds_frags(c, 0, 0, a0, b0);

    for (int t = 0; t < ntiles; t++) {
        if (t + NSTAGE - 1 < ntiles)
            load_tile(c, Ag, strideA, Bg, strideB, t + NSTAGE - 1);
        CP_COMMIT();                     // uniform group count per iter
        lds_frags(c, t, 1, a1, b1);      // overlaps with mma below
        mma_all(acc, a0, b0);
        if (t + 1 < ntiles) {
            CP_WAITG2();                 // tile t+1 resident
            __syncthreads();
            lds_frags(c, t + 1, 0, a0, b0);  // overlaps with mma below
        }
        mma_all(acc, a1, b1);
    }
}

// ---------------------------------------------------------------------------
// Kernel 4: support = d_i * ( adj_h @ xsT^T + d_i * x_i )   -> fp16
// ---------------------------------------------------------------------------
__global__ __launch_bounds__(256, 2) void gemm1_h(const float* __restrict__ x) {
    extern __shared__ __align__(128) char dyn[];
    GemmCore c;
    core_init(c, dyn, blockIdx.x);

    float acc[4][4][4];
#pragma unroll
    for (int i = 0; i < 4; i++)
#pragma unroll
        for (int j = 0; j < 4; j++)
#pragma unroll
            for (int q = 0; q < 4; q++) acc[i][j][q] = 0.f;

    gemm_mainloop(c, g_adj_h, NROWS, g_xsT, NROWS, NT1, acc);

    // epilogue: support = half( d_m * (acc + d_m * x) )
    const int g = c.lane >> 2, tg = c.lane & 3;
#pragma unroll
    for (int i = 0; i < 4; i++) {
        const int r0 = c.m0 + c.wm + 16 * i + g;
        const int r1 = r0 + 8;
        const float d0 = g_deg[r0], d1 = g_deg[r1];
#pragma unroll
        for (int j = 0; j < 4; j++) {
            const int col = c.n0 + c.wn + 8 * j + 2 * tg;
            float2 x0 = *reinterpret_cast<const float2*>(&x[(size_t)r0 * DIN + col]);
            float2 x1 = *reinterpret_cast<const float2*>(&x[(size_t)r1 * DIN + col]);
            __half2 h0 = __floats2half2_rn(d0 * (acc[i][j][0] + d0 * x0.x),
                                           d0 * (acc[i][j][1] + d0 * x0.y));
            __half2 h1 = __floats2half2_rn(d1 * (acc[i][j][2] + d1 * x1.x),
                                           d1 * (acc[i][j][3] + d1 * x1.y));
            *reinterpret_cast<__half2*>(&g_support[(size_t)r0 * DIN + col]) = h0;
            *reinterpret_cast<__half2*>(&g_support[(size_t)r1 * DIN + col]) = h1;
        }
    }
}

// ---------------------------------------------------------------------------
// Kernel 5: out = relu(support @ Wh^T + b)   -> fp32
// ---------------------------------------------------------------------------
__global__ __launch_bounds__(256, 2) void gemm2_h(const float* __restrict__ bias,
                                                  float* __restrict__ out) {
    extern __shared__ __align__(128) char dyn[];
    GemmCore c;
    core_init(c, dyn, blockIdx.x);

    float acc[4][4][4];
#pragma unroll
    for (int i = 0; i < 4; i++)
#pragma unroll
        for (int j = 0; j < 4; j++)
#pragma unroll
            for (int q = 0; q < 4; q++) acc[i][j][q] = 0.f;

    gemm_mainloop(c, g_support, DIN, g_Wh, DIN, NT2, acc);

    const int g = c.lane >> 2, tg = c.lane & 3;
#pragma unroll
    for (int i = 0; i < 4; i++) {
        const int r0 = c.m0 + c.wm + 16 * i + g;
        const int r1 = r0 + 8;
#pragma unroll
        for (int j = 0; j < 4; j++) {
            const int col = c.n0 + c.wn + 8 * j + 2 * tg;
            float2 bv = *reinterpret_cast<const float2*>(&bias[col]);
            float2 o0, o1;
            o0.x = fmaxf(acc[i][j][0] + bv.x, 0.f);
            o0.y = fmaxf(acc[i][j][1] + bv.y, 0.f);
            o1.x = fmaxf(acc[i][j][2] + bv.x, 0.f);
            o1.y = fmaxf(acc[i][j][3] + bv.y, 0.f);
            *reinterpret_cast<float2*>(&out[(size_t)r0 * DOUT + col]) = o0;
            *reinterpret_cast<float2*>(&out[(size_t)r1 * DOUT + col]) = o1;
        }
    }
}

// ---------------------------------------------------------------------------
extern "C" void kernel_launch(void* const* d_in, const int* in_sizes, int n_in,
                              void* d_out, int out_size) {
    const float* x = nullptr;
    const float* adj = nullptr;
    const float* W = nullptr;
    const float* b = nullptr;
    for (int i = 0; i < n_in; i++) {
        long sz = (long)in_sizes[i];
        if (sz == (long)NROWS * NROWS)      adj = (const float*)d_in[i];
        else if (sz == (long)NROWS * DIN)   x   = (const float*)d_in[i];
        else if (sz == (long)DIN * DOUT)    W   = (const float*)d_in[i];
        else if (sz == (long)DOUT)          b   = (const float*)d_in[i];
    }
    float* out = (float*)d_out;

    cudaFuncSetAttribute(gemm1_h, cudaFuncAttributeMaxDynamicSharedMemorySize, DYN_SMEM);
    cudaFuncSetAttribute(gemm2_h, cudaFuncAttributeMaxDynamicSharedMemorySize, DYN_SMEM);

    rowsum_convert<<<NROWS, 256>>>(adj);
    scale_transpose_h<<<dim3(NROWS / 32, DIN / 32), 256>>>(x);
    w_convert<<<(DOUT * DIN / 4) / 256, 256>>>(W);
    gemm1_h<<<(NROWS / CTAM) * (DIN / CTAN), 256, DYN_SMEM>>>(x);
    gemm2_h<<<(NROWS / CTAM) * (DOUT / CTAN), 256, DYN_SMEM>>>(b, out);
}

// round 10
// speedup vs baseline: 1.0758x; 1.0758x over previous
#include <cuda_runtime.h>
#include <cuda_fp16.h>
#include <cstdint>

#define NROWS 8192
#define DIN   512
#define DOUT  512

// ---------------- fp16 mma.sync gemm tiling (R4 geometry) ----------------
#define CTAM 128
#define CTAN 256
#define CTAK 32
#define NSTAGE 5
#define ROWB 80                     // 32 halves data + 16B pad
#define ABYTES (CTAM * ROWB)        // 10240
#define BBYTES (CTAN * ROWB)        // 20480
#define STAGEB (ABYTES + BBYTES)    // 30720
#define DYN_SMEM (STAGEB * NSTAGE)  // 153600

#define NT1 (NROWS / CTAK)          // 256 k-tiles for gemm1 (even)
#define NT2 (DIN / CTAK)            // 16 k-tiles for gemm2 (even)

// Scratch (allocation-free)
__device__ __half g_adj_h[(size_t)NROWS * NROWS];    // fp16 adjacency
__device__ float  g_deg[NROWS];
__device__ __half g_xsT[(size_t)DIN * NROWS];        // xsT[n][k] = half(d_k * x[k][n])
__device__ __half g_support[(size_t)NROWS * DIN];    // fp16 intermediate
__device__ __half g_Wh[(size_t)DOUT * DIN];          // fp16 weights [n][k]

// ======================= PTX helpers =======================
__device__ __forceinline__ uint32_t smem_u32(const void* p) {
    uint32_t a;
    asm("{ .reg .u64 t; cvta.to.shared.u64 t, %1; cvt.u32.u64 %0, t; }" : "=r"(a) : "l"(p));
    return a;
}

__device__ __forceinline__ uint32_t h2_bits(__half2 h) {
    return *reinterpret_cast<uint32_t*>(&h);
}

#define CP_ASYNC16(dst, src) \
    asm volatile("cp.async.cg.shared.global [%0], [%1], 16;" :: "r"(dst), "l"(src))
#define CP_COMMIT() asm volatile("cp.async.commit_group;" ::: "memory")
#define CP_WAITG1() asm volatile("cp.async.wait_group 1;" ::: "memory")
#define CP_WAITG2() asm volatile("cp.async.wait_group 2;" ::: "memory")

#define LDSM4(r0, r1, r2, r3, addr)                                             \
    asm volatile("ldmatrix.sync.aligned.m8n8.x4.shared.b16 {%0,%1,%2,%3}, [%4];"\
                 : "=r"(r0), "=r"(r1), "=r"(r2), "=r"(r3) : "r"(addr))

#define MMA_F16(d, a, b0, b1)                                                   \
    asm volatile(                                                               \
        "mma.sync.aligned.m16n8k16.row.col.f32.f16.f16.f32 "                    \
        "{%0,%1,%2,%3}, {%4,%5,%6,%7}, {%8,%9}, {%0,%1,%2,%3};"                 \
        : "+f"((d)[0]), "+f"((d)[1]), "+f"((d)[2]), "+f"((d)[3])                \
        : "r"((a)[0]), "r"((a)[1]), "r"((a)[2]), "r"((a)[3]),                   \
          "r"(b0), "r"(b1))

// ---------------------------------------------------------------------------
// Kernel 1: d[i] = rsqrt(1 + sum_j adj[i][j])  AND  g_adj_h = half(adj)
// ---------------------------------------------------------------------------
__global__ __launch_bounds__(256) void rowsum_convert(const float* __restrict__ adj) {
    const int row = blockIdx.x;
    const float4* p = reinterpret_cast<const float4*>(adj + (size_t)row * NROWS);
    uint4* dst = reinterpret_cast<uint4*>(g_adj_h + (size_t)row * NROWS);
    float s = 0.f;
    for (int i = threadIdx.x; i < NROWS / 8; i += 256) {
        float4 v0 = p[2 * i + 0];
        float4 v1 = p[2 * i + 1];
        s += ((v0.x + v0.y) + (v0.z + v0.w)) + ((v1.x + v1.y) + (v1.z + v1.w));
        uint4 o;
        o.x = h2_bits(__floats2half2_rn(v0.x, v0.y));
        o.y = h2_bits(__floats2half2_rn(v0.z, v0.w));
        o.z = h2_bits(__floats2half2_rn(v1.x, v1.y));
        o.w = h2_bits(__floats2half2_rn(v1.z, v1.w));
        dst[i] = o;
    }
#pragma unroll
    for (int o = 16; o > 0; o >>= 1) s += __shfl_xor_sync(0xffffffffu, s, o);
    __shared__ float ws[8];
    if ((threadIdx.x & 31) == 0) ws[threadIdx.x >> 5] = s;
    __syncthreads();
    if (threadIdx.x == 0) {
        float t = 0.f;
#pragma unroll
        for (int i = 0; i < 8; i++) t += ws[i];
        g_deg[row] = rsqrtf(1.0f + t);
    }
}

// ---------------------------------------------------------------------------
// Kernel 2: xsT[n][k] = half( d_k * x[k][n] )   (scaled transpose)
// ---------------------------------------------------------------------------
__global__ __launch_bounds__(256) void scale_transpose_h(const float* __restrict__ x) {
    __shared__ float tile[32][33];
    const int kb = blockIdx.x * 32;
    const int nb = blockIdx.y * 32;
    const int tx = threadIdx.x & 31;
    const int ty = threadIdx.x >> 5;
#pragma unroll
    for (int i = 0; i < 32; i += 8) {
        int k = kb + ty + i;
        tile[ty + i][tx] = g_deg[k] * x[(size_t)k * DIN + nb + tx];
    }
    __syncthreads();
#pragma unroll
    for (int i = 0; i < 32; i += 8) {
        int n = nb + ty + i;
        g_xsT[(size_t)n * NROWS + kb + tx] = __float2half_rn(tile[tx][ty + i]);
    }
}

// ---------------------------------------------------------------------------
// Kernel 3: W fp32 -> fp16
// ---------------------------------------------------------------------------
__global__ __launch_bounds__(256) void w_convert(const float* __restrict__ W) {
    const int i = blockIdx.x * 256 + threadIdx.x;
    float4 v = reinterpret_cast<const float4*>(W)[i];
    __half2* d = reinterpret_cast<__half2*>(g_Wh) + 2 * i;
    d[0] = __floats2half2_rn(v.x, v.y);
    d[1] = __floats2half2_rn(v.z, v.w);
}

// ===========================================================================
// Gemm core: CTA 128x256, 8 warps (2m x 4n) of 64x64, BK=32, 5-stage cp.async,
// pair-scheduled mainloop: ONE barrier per TWO k-tiles.
// ===========================================================================
struct GemmCore {
    uint32_t sbase;
    int m0, n0, wm, wn, lane;
    uint32_t aoff, boff;
};

__device__ __forceinline__ void core_init(GemmCore& c, char* dyn, int bid) {
    const int tid = threadIdx.x;
    const int wid = tid >> 5;
    c.lane = tid & 31;
    c.m0 = (bid >> 1) * CTAM;
    c.n0 = (bid & 1) * CTAN;
    c.wm = (wid & 1) * 64;
    c.wn = (wid >> 1) * 64;
    c.sbase = smem_u32(dyn);
    const int l = c.lane;
    c.aoff = (uint32_t)((l & 15) * ROWB + ((l >> 4) & 1) * 16);
    c.boff = (uint32_t)(((l & 7) + ((l >> 4) & 1) * 8) * ROWB + ((l >> 3) & 1) * 16);
}

// Load one 32-k tile into its stage slot (slot = t % 5).
__device__ __forceinline__ void load_tile(const GemmCore& c,
                                          const __half* __restrict__ Ag, int strideA,
                                          const __half* __restrict__ Bg, int strideB,
                                          int t) {
    const int tid = threadIdx.x;
    const int k0 = t * CTAK;
    const uint32_t stA = c.sbase + (uint32_t)(t % NSTAGE) * STAGEB;
    const uint32_t stB = stA + ABYTES;
#pragma unroll
    for (int i = 0; i < 2; i++) {
        int ch = tid + i * 256;
        int r = ch >> 2, q = ch & 3;
        CP_ASYNC16(stA + (uint32_t)(r * ROWB + q * 16),
                   Ag + (size_t)(c.m0 + r) * strideA + k0 + q * 8);
    }
#pragma unroll
    for (int i = 0; i < 4; i++) {
        int ch = tid + i * 256;
        int r = ch >> 2, q = ch & 3;
        CP_ASYNC16(stB + (uint32_t)(r * ROWB + q * 16),
                   Bg + (size_t)(c.n0 + r) * strideB + k0 + q * 8);
    }
}

// Load all fragments for k-half s (s in {0,1}) of tile t.
__device__ __forceinline__ void lds_frags(const GemmCore& c, int t, int s,
                                          uint32_t a[4][4], uint32_t b[8][2]) {
    const uint32_t stA = c.sbase + (uint32_t)(t % NSTAGE) * STAGEB;
    const uint32_t stB = stA + ABYTES;
#pragma unroll
    for (int i = 0; i < 4; i++)
        LDSM4(a[i][0], a[i][1], a[i][2], a[i][3],
              stA + (uint32_t)((c.wm + 16 * i) * ROWB + s * 32) + c.aoff);
#pragma unroll
    for (int jp = 0; jp < 4; jp++)
        LDSM4(b[2 * jp][0], b[2 * jp][1], b[2 * jp + 1][0], b[2 * jp + 1][1],
              stB + (uint32_t)((c.wn + 16 * jp) * ROWB + s * 32) + c.boff);
}

__device__ __forceinline__ void mma_all(float acc[4][8][4],
                                        uint32_t a[4][4], uint32_t b[8][2]) {
#pragma unroll
    for (int i = 0; i < 4; i++)
#pragma unroll
        for (int j = 0; j < 8; j++)
            MMA_F16(acc[i][j], a[i], b[j][0], b[j][1]);
}

// Pair-scheduled pipelined mainloop (ntiles must be even).
// Commit accounting: prologue commits groups for tiles 0,1,2; each pair
// commits exactly 2 groups. wait_group 2 in pair p completes through the
// group of tile t+2, leaving (t+3, t+4) in flight.
__device__ __forceinline__ void gemm_mainloop(const GemmCore& c,
                                              const __half* __restrict__ Ag, int strideA,
                                              const __half* __restrict__ Bg, int strideB,
                                              int ntiles, float acc[4][8][4]) {
    load_tile(c, Ag, strideA, Bg, strideB, 0);
    CP_COMMIT();
    load_tile(c, Ag, strideA, Bg, strideB, 1);
    CP_COMMIT();
    load_tile(c, Ag, strideA, Bg, strideB, 2);
    CP_COMMIT();
    CP_WAITG1();                 // tiles 0,1 resident
    __syncthreads();

    uint32_t a0[4][4], b0[8][2], a1[4][4], b1[8][2];
    lds_frags(c, 0, 0, a0, b0);

    const int npairs = ntiles >> 1;
    for (int p = 0; p < npairs; p++) {
        const int t = 2 * p;
        // refill slots of tiles t-2 and t-1 (reads retired before previous barrier)
        if (t + 3 < ntiles)
            load_tile(c, Ag, strideA, Bg, strideB, t + 3);
        CP_COMMIT();
        if (t + 4 < ntiles)
            load_tile(c, Ag, strideA, Bg, strideB, t + 4);
        CP_COMMIT();

        lds_frags(c, t, 1, a1, b1);          // overlaps mma
        mma_all(acc, a0, b0);                // tile t, half 0
        lds_frags(c, t + 1, 0, a0, b0);
        mma_all(acc, a1, b1);                // tile t, half 1
        lds_frags(c, t + 1, 1, a1, b1);
        mma_all(acc, a0, b0);                // tile t+1, half 0

        if (p + 1 < npairs) {
            CP_WAITG2();                     // tile t+2 resident
            __syncthreads();                 // retire reads of tiles t, t+1
            lds_frags(c, t + 2, 0, a0, b0);  // overlaps trailing mma
        }
        mma_all(acc, a1, b1);                // tile t+1, half 1
    }
}

// ---------------------------------------------------------------------------
// Kernel 4: support = d_i * ( adj_h @ xsT^T + d_i * x_i )   -> fp16
// ---------------------------------------------------------------------------
__global__ __launch_bounds__(256, 1) void gemm1_h(const float* __restrict__ x) {
    extern __shared__ __align__(128) char dyn[];
    GemmCore c;
    core_init(c, dyn, blockIdx.x);

    float acc[4][8][4];
#pragma unroll
    for (int i = 0; i < 4; i++)
#pragma unroll
        for (int j = 0; j < 8; j++)
#pragma unroll
            for (int q = 0; q < 4; q++) acc[i][j][q] = 0.f;

    gemm_mainloop(c, g_adj_h, NROWS, g_xsT, NROWS, NT1, acc);

    // epilogue: support = half( d_m * (acc + d_m * x) )
    const int g = c.lane >> 2, tg = c.lane & 3;
#pragma unroll
    for (int i = 0; i < 4; i++) {
        const int r0 = c.m0 + c.wm + 16 * i + g;
        const int r1 = r0 + 8;
        const float d0 = g_deg[r0], d1 = g_deg[r1];
#pragma unroll
        for (int j = 0; j < 8; j++) {
            const int col = c.n0 + c.wn + 8 * j + 2 * tg;
            float2 x0 = *reinterpret_cast<const float2*>(&x[(size_t)r0 * DIN + col]);
            float2 x1 = *reinterpret_cast<const float2*>(&x[(size_t)r1 * DIN + col]);
            __half2 h0 = __floats2half2_rn(d0 * (acc[i][j][0] + d0 * x0.x),
                                           d0 * (acc[i][j][1] + d0 * x0.y));
            __half2 h1 = __floats2half2_rn(d1 * (acc[i][j][2] + d1 * x1.x),
                                           d1 * (acc[i][j][3] + d1 * x1.y));
            *reinterpret_cast<__half2*>(&g_support[(size_t)r0 * DIN + col]) = h0;
            *reinterpret_cast<__half2*>(&g_support[(size_t)r1 * DIN + col]) = h1;
        }
    }
}

// ---------------------------------------------------------------------------
// Kernel 5: out = relu(support @ Wh^T + b)   -> fp32
// ---------------------------------------------------------------------------
__global__ __launch_bounds__(256, 1) void gemm2_h(const float* __restrict__ bias,
                                                  float* __restrict__ out) {
    extern __shared__ __align__(128) char dyn[];
    GemmCore c;
    core_init(c, dyn, blockIdx.x);

    float acc[4][8][4];
#pragma unroll
    for (int i = 0; i < 4; i++)
#pragma unroll
        for (int j = 0; j < 8; j++)
#pragma unroll
            for (int q = 0; q < 4; q++) acc[i][j][q] = 0.f;

    gemm_mainloop(c, g_support, DIN, g_Wh, DIN, NT2, acc);

    const int g = c.lane >> 2, tg = c.lane & 3;
#pragma unroll
    for (int i = 0; i < 4; i++) {
        const int r0 = c.m0 + c.wm + 16 * i + g;
        const int r1 = r0 + 8;
#pragma unroll
        for (int j = 0; j < 8; j++) {
            const int col = c.n0 + c.wn + 8 * j + 2 * tg;
            float2 bv = *reinterpret_cast<const float2*>(&bias[col]);
            float2 o0, o1;
            o0.x = fmaxf(acc[i][j][0] + bv.x, 0.f);
            o0.y = fmaxf(acc[i][j][1] + bv.y, 0.f);
            o1.x = fmaxf(acc[i][j][2] + bv.x, 0.f);
            o1.y = fmaxf(acc[i][j][3] + bv.y, 0.f);
            *reinterpret_cast<float2*>(&out[(size_t)r0 * DOUT + col]) = o0;
            *reinterpret_cast<float2*>(&out[(size_t)r1 * DOUT + col]) = o1;
        }
    }
}

// ---------------------------------------------------------------------------
extern "C" void kernel_launch(void* const* d_in, const int* in_sizes, int n_in,
                              void* d_out, int out_size) {
    const float* x = nullptr;
    const float* adj = nullptr;
    const float* W = nullptr;
    const float* b = nullptr;
    for (int i = 0; i < n_in; i++) {
        long sz = (long)in_sizes[i];
        if (sz == (long)NROWS * NROWS)      adj = (const float*)d_in[i];
        else if (sz == (long)NROWS * DIN)   x   = (const float*)d_in[i];
        else if (sz == (long)DIN * DOUT)    W   = (const float*)d_in[i];
        else if (sz == (long)DOUT)          b   = (const float*)d_in[i];
    }
    float* out = (float*)d_out;

    cudaFuncSetAttribute(gemm1_h, cudaFuncAttributeMaxDynamicSharedMemorySize, DYN_SMEM);
    cudaFuncSetAttribute(gemm2_h, cudaFuncAttributeMaxDynamicSharedMemorySize, DYN_SMEM);

    w_convert<<<(DOUT * DIN / 4) / 256, 256>>>(W);
    rowsum_convert<<<NROWS, 256>>>(adj);
    scale_transpose_h<<<dim3(NROWS / 32, DIN / 32), 256>>>(x);
    gemm1_h<<<(NROWS / CTAM) * (DIN / CTAN), 256, DYN_SMEM>>>(x);
    gemm2_h<<<(NROWS / CTAM) * (DOUT / CTAN), 256, DYN_SMEM>>>(b, out);
}

// round 11
// speedup vs baseline: 1.2766x; 1.1866x over previous
#include <cuda_runtime.h>
#include <cuda_fp16.h>
#include <cstdint>

#define NROWS 8192
#define DIN   512
#define DOUT  512

// ---------------- fp16 mma.sync gemm tiling (R4 geometry) ----------------
#define CTAM 128
#define CTAN 256
#define CTAK 32
#define NSTAGE 4
#define ROWB 80                     // 32 halves data + 16B pad
#define ABYTES (CTAM * ROWB)        // 10240
#define BBYTES (CTAN * ROWB)        // 20480
#define STAGEB (ABYTES + BBYTES)    // 30720
#define DYN_SMEM (STAGEB * NSTAGE)  // 122880

#define NT1 (NROWS / CTAK)          // 256 k-tiles for gemm1
#define NT2 (DIN / CTAK)            // 16 k-tiles for gemm2

// Scratch (allocation-free)
__device__ __half g_adj_h[(size_t)NROWS * NROWS];    // fp16 adjacency
__device__ float  g_deg[NROWS];
__device__ __half g_xsT[(size_t)DIN * NROWS];        // xsT[n][k] = half(d_k * x[k][n])
__device__ __half g_support[(size_t)NROWS * DIN];    // fp16 intermediate
__device__ __half g_Wh[(size_t)DOUT * DIN];          // fp16 weights [n][k]

// ======================= PTX helpers =======================
__device__ __forceinline__ uint32_t smem_u32(const void* p) {
    uint32_t a;
    asm("{ .reg .u64 t; cvta.to.shared.u64 t, %1; cvt.u32.u64 %0, t; }" : "=r"(a) : "l"(p));
    return a;
}

__device__ __forceinline__ uint32_t h2_bits(__half2 h) {
    return *reinterpret_cast<uint32_t*>(&h);
}

#define CP_ASYNC16(dst, src) \
    asm volatile("cp.async.cg.shared.global [%0], [%1], 16;" :: "r"(dst), "l"(src))
#define CP_COMMIT() asm volatile("cp.async.commit_group;" ::: "memory")
#define CP_WAITG2() asm volatile("cp.async.wait_group 2;" ::: "memory")

#define LDSM4(r0, r1, r2, r3, addr)                                             \
    asm volatile("ldmatrix.sync.aligned.m8n8.x4.shared.b16 {%0,%1,%2,%3}, [%4];"\
                 : "=r"(r0), "=r"(r1), "=r"(r2), "=r"(r3) : "r"(addr))

#define MMA_F16(d, a, b0, b1)                                                   \
    asm volatile(                                                               \
        "mma.sync.aligned.m16n8k16.row.col.f32.f16.f16.f32 "                    \
        "{%0,%1,%2,%3}, {%4,%5,%6,%7}, {%8,%9}, {%0,%1,%2,%3};"                 \
        : "+f"((d)[0]), "+f"((d)[1]), "+f"((d)[2]), "+f"((d)[3])                \
        : "r"((a)[0]), "r"((a)[1]), "r"((a)[2]), "r"((a)[3]),                   \
          "r"(b0), "r"(b1))

// ---------------------------------------------------------------------------
// Kernel 1: d[i] = rsqrt(1 + sum_j adj[i][j])  AND  g_adj_h = half(adj)
//   Streaming loads/stores (data is dead in cache after this kernel),
//   2x unroll for MLP.
// ---------------------------------------------------------------------------
__global__ __launch_bounds__(256) void rowsum_convert(const float* __restrict__ adj) {
    const int row = blockIdx.x;
    const float4* p = reinterpret_cast<const float4*>(adj + (size_t)row * NROWS);
    uint4* dst = reinterpret_cast<uint4*>(g_adj_h + (size_t)row * NROWS);
    float s = 0.f;
    // NROWS/8 = 1024 uint4-chunks per row; 256 threads x 4 iters, unrolled x2.
#pragma unroll 2
    for (int i = threadIdx.x; i < NROWS / 8; i += 256) {
        float4 v0 = __ldcs(&p[2 * i + 0]);
        float4 v1 = __ldcs(&p[2 * i + 1]);
        s += ((v0.x + v0.y) + (v0.z + v0.w)) + ((v1.x + v1.y) + (v1.z + v1.w));
        uint4 o;
        o.x = h2_bits(__floats2half2_rn(v0.x, v0.y));
        o.y = h2_bits(__floats2half2_rn(v0.z, v0.w));
        o.z = h2_bits(__floats2half2_rn(v1.x, v1.y));
        o.w = h2_bits(__floats2half2_rn(v1.z, v1.w));
        __stcs(&dst[i], o);
    }
#pragma unroll
    for (int o = 16; o > 0; o >>= 1) s += __shfl_xor_sync(0xffffffffu, s, o);
    __shared__ float ws[8];
    if ((threadIdx.x & 31) == 0) ws[threadIdx.x >> 5] = s;
    __syncthreads();
    if (threadIdx.x == 0) {
        float t = 0.f;
#pragma unroll
        for (int i = 0; i < 8; i++) t += ws[i];
        g_deg[row] = rsqrtf(1.0f + t);
    }
}

// ---------------------------------------------------------------------------
// Kernel 2: xsT[n][k] = half( d_k * x[k][n] )   (scaled transpose)
// ---------------------------------------------------------------------------
__global__ __launch_bounds__(256) void scale_transpose_h(const float* __restrict__ x) {
    __shared__ float tile[32][33];
    const int kb = blockIdx.x * 32;
    const int nb = blockIdx.y * 32;
    const int tx = threadIdx.x & 31;
    const int ty = threadIdx.x >> 5;
#pragma unroll
    for (int i = 0; i < 32; i += 8) {
        int k = kb + ty + i;
        tile[ty + i][tx] = g_deg[k] * x[(size_t)k * DIN + nb + tx];
    }
    __syncthreads();
#pragma unroll
    for (int i = 0; i < 32; i += 8) {
        int n = nb + ty + i;
        g_xsT[(size_t)n * NROWS + kb + tx] = __float2half_rn(tile[tx][ty + i]);
    }
}

// ---------------------------------------------------------------------------
// Kernel 3: W fp32 -> fp16
// ---------------------------------------------------------------------------
__global__ __launch_bounds__(256) void w_convert(const float* __restrict__ W) {
    const int i = blockIdx.x * 256 + threadIdx.x;
    float4 v = reinterpret_cast<const float4*>(W)[i];
    __half2* d = reinterpret_cast<__half2*>(g_Wh) + 2 * i;
    d[0] = __floats2half2_rn(v.x, v.y);
    d[1] = __floats2half2_rn(v.z, v.w);
}

// ===========================================================================
// Gemm core (EXACT R4): CTA 128x256, 8 warps (2m x 4n) of 64x64, BK=32,
// 4-stage cp.async, double-buffered ldmatrix fragments.
// ===========================================================================
struct GemmCore {
    uint32_t sbase;
    int m0, n0, wm, wn, lane;
    uint32_t aoff, boff;
};

__device__ __forceinline__ void core_init(GemmCore& c, char* dyn, int bid) {
    const int tid = threadIdx.x;
    const int wid = tid >> 5;
    c.lane = tid & 31;
    c.m0 = (bid >> 1) * CTAM;
    c.n0 = (bid & 1) * CTAN;
    c.wm = (wid & 1) * 64;
    c.wn = (wid >> 1) * 64;
    c.sbase = smem_u32(dyn);
    const int l = c.lane;
    c.aoff = (uint32_t)((l & 15) * ROWB + ((l >> 4) & 1) * 16);
    c.boff = (uint32_t)(((l & 7) + ((l >> 4) & 1) * 8) * ROWB + ((l >> 3) & 1) * 16);
}

__device__ __forceinline__ void load_tile(const GemmCore& c,
                                          const __half* __restrict__ Ag, int strideA,
                                          const __half* __restrict__ Bg, int strideB,
                                          int t) {
    const int tid = threadIdx.x;
    const int k0 = t * CTAK;
    const uint32_t stA = c.sbase + (uint32_t)(t & (NSTAGE - 1)) * STAGEB;
    const uint32_t stB = stA + ABYTES;
#pragma unroll
    for (int i = 0; i < 2; i++) {
        int ch = tid + i * 256;
        int r = ch >> 2, q = ch & 3;
        CP_ASYNC16(stA + (uint32_t)(r * ROWB + q * 16),
                   Ag + (size_t)(c.m0 + r) * strideA + k0 + q * 8);
    }
#pragma unroll
    for (int i = 0; i < 4; i++) {
        int ch = tid + i * 256;
        int r = ch >> 2, q = ch & 3;
        CP_ASYNC16(stB + (uint32_t)(r * ROWB + q * 16),
                   Bg + (size_t)(c.n0 + r) * strideB + k0 + q * 8);
    }
}

// Load all fragments for k-half s (s in {0,1}) of tile t.
__device__ __forceinline__ void lds_frags(const GemmCore& c, int t, int s,
                                          uint32_t a[4][4], uint32_t b[8][2]) {
    const uint32_t stA = c.sbase + (uint32_t)(t & (NSTAGE - 1)) * STAGEB;
    const uint32_t stB = stA + ABYTES;
#pragma unroll
    for (int i = 0; i < 4; i++)
        LDSM4(a[i][0], a[i][1], a[i][2], a[i][3],
              stA + (uint32_t)((c.wm + 16 * i) * ROWB + s * 32) + c.aoff);
#pragma unroll
    for (int jp = 0; jp < 4; jp++)
        LDSM4(b[2 * jp][0], b[2 * jp][1], b[2 * jp + 1][0], b[2 * jp + 1][1],
              stB + (uint32_t)((c.wn + 16 * jp) * ROWB + s * 32) + c.boff);
}

__device__ __forceinline__ void mma_all(float acc[4][8][4],
                                        uint32_t a[4][4], uint32_t b[8][2]) {
#pragma unroll
    for (int i = 0; i < 4; i++)
#pragma unroll
        for (int j = 0; j < 8; j++)
            MMA_F16(acc[i][j], a[i], b[j][0], b[j][1]);
}

// Pipelined mainloop shared by both gemms (EXACT R4 schedule).
__device__ __forceinline__ void gemm_mainloop(const GemmCore& c,
                                              const __half* __restrict__ Ag, int strideA,
                                              const __half* __restrict__ Bg, int strideB,
                                              int ntiles, float acc[4][8][4]) {
    // prologue: stages 0..2
#pragma unroll
    for (int s = 0; s < NSTAGE - 1; s++) {
        load_tile(c, Ag, strideA, Bg, strideB, s);
        CP_COMMIT();
    }
    CP_WAITG2();                 // tile 0 resident
    __syncthreads();

    uint32_t a0[4][4], b0[8][2], a1[4][4], b1[8][2];
    lds_frags(c, 0, 0, a0, b0);

    for (int t = 0; t < ntiles; t++) {
        if (t + NSTAGE - 1 < ntiles)
            load_tile(c, Ag, strideA, Bg, strideB, t + NSTAGE - 1);
        CP_COMMIT();                     // uniform group count per iter
        lds_frags(c, t, 1, a1, b1);      // overlaps with mma below
        mma_all(acc, a0, b0);
        if (t + 1 < ntiles) {
            CP_WAITG2();                 // tile t+1 resident
            __syncthreads();             // stage slot (t+3)&3 safe to refill next iter
            lds_frags(c, t + 1, 0, a0, b0);  // overlaps with mma below
        }
        mma_all(acc, a1, b1);
    }
}

// ---------------------------------------------------------------------------
// Kernel 4: support = d_i * ( adj_h @ xsT^T + d_i * x_i )   -> fp16
// ---------------------------------------------------------------------------
__global__ __launch_bounds__(256, 1) void gemm1_h(const float* __restrict__ x) {
    extern __shared__ __align__(128) char dyn[];
    GemmCore c;
    core_init(c, dyn, blockIdx.x);

    float acc[4][8][4];
#pragma unroll
    for (int i = 0; i < 4; i++)
#pragma unroll
        for (int j = 0; j < 8; j++)
#pragma unroll
            for (int q = 0; q < 4; q++) acc[i][j][q] = 0.f;

    gemm_mainloop(c, g_adj_h, NROWS, g_xsT, NROWS, NT1, acc);

    // epilogue: support = half( d_m * (acc + d_m * x) )
    const int g = c.lane >> 2, tg = c.lane & 3;
#pragma unroll
    for (int i = 0; i < 4; i++) {
        const int r0 = c.m0 + c.wm + 16 * i + g;
        const int r1 = r0 + 8;
        const float d0 = g_deg[r0], d1 = g_deg[r1];
#pragma unroll
        for (int j = 0; j < 8; j++) {
            const int col = c.n0 + c.wn + 8 * j + 2 * tg;
            float2 x0 = *reinterpret_cast<const float2*>(&x[(size_t)r0 * DIN + col]);
            float2 x1 = *reinterpret_cast<const float2*>(&x[(size_t)r1 * DIN + col]);
            __half2 h0 = __floats2half2_rn(d0 * (acc[i][j][0] + d0 * x0.x),
                                           d0 * (acc[i][j][1] + d0 * x0.y));
            __half2 h1 = __floats2half2_rn(d1 * (acc[i][j][2] + d1 * x1.x),
                                           d1 * (acc[i][j][3] + d1 * x1.y));
            *reinterpret_cast<__half2*>(&g_support[(size_t)r0 * DIN + col]) = h0;
            *reinterpret_cast<__half2*>(&g_support[(size_t)r1 * DIN + col]) = h1;
        }
    }
}

// ---------------------------------------------------------------------------
// Kernel 5: out = relu(support @ Wh^T + b)   -> fp32
// ---------------------------------------------------------------------------
__global__ __launch_bounds__(256, 1) void gemm2_h(const float* __restrict__ bias,
                                                  float* __restrict__ out) {
    extern __shared__ __align__(128) char dyn[];
    GemmCore c;
    core_init(c, dyn, blockIdx.x);

    float acc[4][8][4];
#pragma unroll
    for (int i = 0; i < 4; i++)
#pragma unroll
        for (int j = 0; j < 8; j++)
#pragma unroll
            for (int q = 0; q < 4; q++) acc[i][j][q] = 0.f;

    gemm_mainloop(c, g_support, DIN, g_Wh, DIN, NT2, acc);

    const int g = c.lane >> 2, tg = c.lane & 3;
#pragma unroll
    for (int i = 0; i < 4; i++) {
        const int r0 = c.m0 + c.wm + 16 * i + g;
        const int r1 = r0 + 8;
#pragma unroll
        for (int j = 0; j < 8; j++) {
            const int col = c.n0 + c.wn + 8 * j + 2 * tg;
            float2 bv = *reinterpret_cast<const float2*>(&bias[col]);
            float2 o0, o1;
            o0.x = fmaxf(acc[i][j][0] + bv.x, 0.f);
            o0.y = fmaxf(acc[i][j][1] + bv.y, 0.f);
            o1.x = fmaxf(acc[i][j][2] + bv.x, 0.f);
            o1.y = fmaxf(acc[i][j][3] + bv.y, 0.f);
            *reinterpret_cast<float2*>(&out[(size_t)r0 * DOUT + col]) = o0;
            *reinterpret_cast<float2*>(&out[(size_t)r1 * DOUT + col]) = o1;
        }
    }
}

// ---------------------------------------------------------------------------
extern "C" void kernel_launch(void* const* d_in, const int* in_sizes, int n_in,
                              void* d_out, int out_size) {
    const float* x = nullptr;
    const float* adj = nullptr;
    const float* W = nullptr;
    const float* b = nullptr;
    for (int i = 0; i < n_in; i++) {
        long sz = (long)in_sizes[i];
        if (sz == (long)NROWS * NROWS)      adj = (const float*)d_in[i];
        else if (sz == (long)NROWS * DIN)   x   = (const float*)d_in[i];
        else if (sz == (long)DIN * DOUT)    W   = (const float*)d_in[i];
        else if (sz == (long)DOUT)          b   = (const float*)d_in[i];
    }
    float* out = (float*)d_out;

    cudaFuncSetAttribute(gemm1_h, cudaFuncAttributeMaxDynamicSharedMemorySize, DYN_SMEM);
    cudaFuncSetAttribute(gemm2_h, cudaFuncAttributeMaxDynamicSharedMemorySize, DYN_SMEM);

    rowsum_convert<<<NROWS, 256>>>(adj);
    scale_transpose_h<<<dim3(NROWS / 32, DIN / 32), 256>>>(x);
    w_convert<<<(DOUT * DIN / 4) / 256, 256>>>(W);
    gemm1_h<<<(NROWS / CTAM) * (DIN / CTAN), 256, DYN_SMEM>>>(x);
    gemm2_h<<<(NROWS / CTAM) * (DOUT / CTAN), 256, DYN_SMEM>>>(b, out);
}